// round 6
// baseline (speedup 1.0000x reference)
#include <cuda_runtime.h>

// out[b, s, d] = in[b, s, d] + PE(s, d)
// B=8, S=4096, D=1024 fp32. Pure HBM-bound streaming add.
//
// R5: 256-bit vector loads/stores (ld/st.global.v8.f32, sm_100+) so each
// warp moves 1KB per instruction and bursts 8KB reads then 8KB writes.
// Goal: coarser same-direction runs at the DRAM controller -> fewer R/W
// bus turnarounds (the mechanism behind the 25% dram-idle plateau).
// Math identical to validated R0/R2 (rel_err 1.27e-5).

#define B 8
#define S 4096
#define D 1024
#define DG (D / 8)            // 128 8-float groups per row
#define NIDX (S * DG)         // 524288 groups per batch image
#define BSTRIDE (S * D)       // 4194304 floats per batch image

// 2*log2(10000)/1024 (double-rounded)
#define NEG_C 0.02595256324130752f

__device__ __forceinline__ void ldg256(const float* p, float* v)
{
    asm volatile("ld.global.cg.v8.f32 {%0,%1,%2,%3,%4,%5,%6,%7}, [%8];"
                 : "=f"(v[0]), "=f"(v[1]), "=f"(v[2]), "=f"(v[3]),
                   "=f"(v[4]), "=f"(v[5]), "=f"(v[6]), "=f"(v[7])
                 : "l"(p));
}

__device__ __forceinline__ void stg256(float* p, const float* v)
{
    asm volatile("st.global.cs.v8.f32 [%0], {%1,%2,%3,%4,%5,%6,%7,%8};"
                 :: "l"(p),
                    "f"(v[0]), "f"(v[1]), "f"(v[2]), "f"(v[3]),
                    "f"(v[4]), "f"(v[5]), "f"(v[6]), "f"(v[7])
                 : "memory");
}

__global__ __launch_bounds__(256, 2) void pe_add_kernel(
    const float* __restrict__ in, float* __restrict__ out)
{
    const int idx = blockIdx.x * 256 + threadIdx.x;   // 0 .. NIDX-1
    const int s  = idx >> 7;                          // row (0..4095)
    const int g  = idx & 127;                         // 8-float group in row
    const long ofs = (long)idx * 8;                   // float offset in image

    // ---- front-batch all 8 batch loads (8 x 256-bit in flight) ----
    float v[B][8];
#pragma unroll
    for (int b = 0; b < B; b++)
        ldg256(in + (long)b * BSTRIDE + ofs, v[b]);

    // ---- PE for this (s, 8-dim group), under the load shadow ----
    const float sf = (float)s;
    const int d0 = g * 8;

    float pe[8];
#pragma unroll
    for (int k = 0; k < 8; k += 2) {
        float we = exp2f((float)(d0 + k)     * -NEG_C);
        float wo = exp2f((float)(d0 + k + 1) * -NEG_C);
        pe[k]     = sinf(sf * we);   // even dim -> sin
        pe[k + 1] = cosf(sf * wo);   // odd dim  -> cos
    }

    // ---- add + 256-bit streaming stores ----
#pragma unroll
    for (int b = 0; b < B; b++) {
        float x[8];
#pragma unroll
        for (int k = 0; k < 8; k++) x[k] = v[b][k] + pe[k];
        stg256(out + (long)b * BSTRIDE + ofs, x);
    }
}

extern "C" void kernel_launch(void* const* d_in, const int* in_sizes, int n_in,
                              void* d_out, int out_size)
{
    (void)in_sizes; (void)n_in; (void)out_size;
    const float* in = (const float*)d_in[0];
    float* out = (float*)d_out;

    // NIDX / 256 = 2048 CTAs
    pe_add_kernel<<<NIDX / 256, 256>>>(in, out);
}